// round 6
// baseline (speedup 1.0000x reference)
#include <cuda_runtime.h>
#include <math.h>

#define G 8192
#define S 64
#define D 128
#define H 256
#define EPS 0.01f

// Output layout: rep [G*D] | mixture [G*8] | scale [G] | alpha [G] | beta [G]
#define O_REP   0
#define O_MIX   (G * D)
#define O_SCALE (O_MIX + G * 8)
#define O_ALPHA (O_SCALE + G)
#define O_BETA  (O_ALPHA + G)

// ---------------------------------------------------------------------------
// Kernel 1: per-group statistics -> rep. Warp per group, 8 outstanding
// LDG.128 per iteration, streaming (.cs) loads on x.
// ---------------------------------------------------------------------------
__global__ __launch_bounds__(256) void stats_kernel(
    const float* __restrict__ x, const float* __restrict__ y,
    const float* __restrict__ ax, const float* __restrict__ ay,
    float* __restrict__ rep)
{
    const int warp = threadIdx.x >> 5;
    const int lane = threadIdx.x & 31;
    const int g = blockIdx.x * 8 + warp;

    const float4* xg = reinterpret_cast<const float4*>(x + (size_t)g * S * D) + lane;
    const float4  a4 = reinterpret_cast<const float4*>(ax + (size_t)g * D)[lane];
    const float   ayv = ay[g];
    const float*  yg = y + (size_t)g * S;

    float sx0 = 0.f, sx1 = 0.f, sx2 = 0.f, sx3 = 0.f;
    float sp0 = 0.f, sp1 = 0.f, sp2 = 0.f, sp3 = 0.f;
    float sxx = 0.f, sy = 0.f;

    for (int s0 = 0; s0 < S; s0 += 8) {
        float4 xv[8];
        float  yv[8];
#pragma unroll
        for (int i = 0; i < 8; ++i) xv[i] = __ldcs(xg + (s0 + i) * 32);
#pragma unroll
        for (int i = 0; i < 8; ++i) yv[i] = __ldg(yg + s0 + i);
#pragma unroll
        for (int i = 0; i < 8; ++i) {
            float xr0 = xv[i].x - a4.x;
            float xr1 = xv[i].y - a4.y;
            float xr2 = xv[i].z - a4.z;
            float xr3 = xv[i].w - a4.w;
            float yr  = yv[i] - ayv;
            sx0 += xr0; sx1 += xr1; sx2 += xr2; sx3 += xr3;
            sp0 += xr0 * yr; sp1 += xr1 * yr; sp2 += xr2 * yr; sp3 += xr3 * yr;
            sxx += xr0 * xr0 + xr1 * xr1 + xr2 * xr2 + xr3 * xr3;
            sy  += yr;
        }
    }

    float tot = sx0 + sx1 + sx2 + sx3;
    float sxxT = sxx;
#pragma unroll
    for (int o = 16; o > 0; o >>= 1) {
        tot  += __shfl_xor_sync(0xffffffffu, tot,  o);
        sxxT += __shfl_xor_sync(0xffffffffu, sxxT, o);
    }

    const float nD = (float)(S * D);
    const float var = (sxxT - tot * tot / nD) / (nD - 1.f);
    const float inv = 1.f / var;
    const float invn  = 1.f / (float)S;
    const float invn1 = 1.f / (float)(S - 1);

    float4 r;
    r.x = (sp0 - sx0 * sy * invn) * invn1 * inv;
    r.y = (sp1 - sx1 * sy * invn) * invn1 * inv;
    r.z = (sp2 - sx2 * sy * invn) * invn1 * inv;
    r.w = (sp3 - sx3 * sy * invn) * invn1 * inv;
    reinterpret_cast<float4*>(rep + (size_t)g * D)[lane] = r;
}

// ---------------------------------------------------------------------------
// Kernel 2: MLP head. Grid = 512 x 256 threads. Block owns 16 groups.
// Warp w owns rows {2w, 2w+1}; lane owns cols lane+32j (j<8).
// Hidden activations stay in registers -> GEMM2 + epilogue per-warp,
// no sH, smem = sA(8K) + sW(32K) + sW2(10K) = 50KB -> 4 CTAs/SM.
// ---------------------------------------------------------------------------
__device__ __forceinline__ float softplus_f(float v) {
    return fmaxf(v, 0.f) + log1pf(expf(-fabsf(v)));
}

#define ROWS 16                 // groups per block
#define KC   32                 // k-chunk depth

__global__ __launch_bounds__(256, 4) void mlp_kernel(
    const float* __restrict__ rep, const float* __restrict__ W1,
    const float* __restrict__ b1, const float* __restrict__ W2,
    const float* __restrict__ b2, float* __restrict__ out)
{
    __shared__ float sA[ROWS * D];      // 8 KB
    __shared__ float sW[KC * H];        // 32 KB
    __shared__ float sW2[H * 10];       // 10 KB

    const int t = threadIdx.x;
    const int warp = t >> 5;
    const int lane = t & 31;

    // load A tile (16 rows of rep) and W2
    {
        const float4* src = reinterpret_cast<const float4*>(rep + (size_t)blockIdx.x * ROWS * D);
        float4* dst = reinterpret_cast<float4*>(sA);
        dst[t] = src[t];
        dst[t + 256] = src[t + 256];
    }
    for (int i = t; i < H * 10; i += 256) sW2[i] = W2[i];

    float acc[2][8];
#pragma unroll
    for (int r = 0; r < 2; ++r)
#pragma unroll
        for (int j = 0; j < 8; ++j) acc[r][j] = 0.f;

    const float* A0 = sA + (warp * 2) * D;
    const float* A1 = A0 + D;

    for (int c = 0; c < D / KC; ++c) {
        // cooperative load of W1 chunk [KC x H] = 2048 float4
        {
            const float4* src = reinterpret_cast<const float4*>(W1 + c * KC * H);
            float4* dst = reinterpret_cast<float4*>(sW);
#pragma unroll
            for (int i = 0; i < 8; ++i) dst[t + i * 256] = src[t + i * 256];
        }
        __syncthreads();

#pragma unroll
        for (int kk = 0; kk < KC; ++kk) {
            const int k = c * KC + kk;
            float a0 = A0[k];                 // broadcast LDS
            float a1 = A1[k];
            const float* wrow = sW + kk * H + lane;
#pragma unroll
            for (int j = 0; j < 8; ++j) {
                float w = wrow[32 * j];
                acc[0][j] += a0 * w;
                acc[1][j] += a1 * w;
            }
        }
        __syncthreads();
    }

    // tanh + GEMM2 + epilogue, all per-warp from registers
    float b1c[8];
#pragma unroll
    for (int j = 0; j < 8; ++j) b1c[j] = __ldg(b1 + lane + 32 * j);

#pragma unroll
    for (int r = 0; r < 2; ++r) {
        float p[10];
#pragma unroll
        for (int k = 0; k < 10; ++k) p[k] = 0.f;

#pragma unroll
        for (int j = 0; j < 8; ++j) {
            float hv = tanhf(acc[r][j] + b1c[j]);
            const float* w2r = sW2 + (lane + 32 * j) * 10;
#pragma unroll
            for (int k = 0; k < 10; ++k) p[k] += hv * w2r[k];
        }
#pragma unroll
        for (int k = 0; k < 10; ++k) {
#pragma unroll
            for (int o = 16; o > 0; o >>= 1)
                p[k] += __shfl_xor_sync(0xffffffffu, p[k], o);
        }

        if (lane == 0) {
            const int g = blockIdx.x * ROWS + warp * 2 + r;
            float o0 = p[0] + __ldg(b2 + 0);
            float o1 = p[1] + __ldg(b2 + 1);
            float alpha = softplus_f(o0) * (1.f - EPS) + EPS;
            float beta  = softplus_f(o1) * (1.f - EPS) + EPS;

            float lg[8];
            float mx = -3.4e38f;
#pragma unroll
            for (int k = 0; k < 8; ++k) {
                lg[k] = p[2 + k] + __ldg(b2 + 2 + k);
                mx = fmaxf(mx, lg[k]);
            }
            float se = 0.f;
#pragma unroll
            for (int k = 0; k < 8; ++k) { lg[k] = expf(lg[k] - mx); se += lg[k]; }
            float inv_se = 1.f / se;
#pragma unroll
            for (int k = 0; k < 8; ++k) out[O_MIX + (size_t)g * 8 + k] = lg[k] * inv_se;

            out[O_SCALE + g] = sqrtf(beta / alpha);
            out[O_ALPHA + g] = alpha;
            out[O_BETA  + g] = beta;
        }
    }
}

// ---------------------------------------------------------------------------
extern "C" void kernel_launch(void* const* d_in, const int* in_sizes, int n_in,
                              void* d_out, int out_size)
{
    (void)in_sizes; (void)n_in; (void)out_size;
    // inputs: 0=index(int32), 1=x, 2=y, 3=anchor_x, 4=anchor_y, 5=W1, 6=b1, 7=W2, 8=b2
    const float* x  = (const float*)d_in[1];
    const float* y  = (const float*)d_in[2];
    const float* ax = (const float*)d_in[3];
    const float* ay = (const float*)d_in[4];
    const float* W1 = (const float*)d_in[5];
    const float* b1 = (const float*)d_in[6];
    const float* W2 = (const float*)d_in[7];
    const float* b2 = (const float*)d_in[8];
    float* out = (float*)d_out;

    stats_kernel<<<G / 8, 256>>>(x, y, ax, ay, out + O_REP);
    mlp_kernel<<<G / ROWS, 256>>>(out + O_REP, W1, b1, W2, b2, out);
}

// round 7
// speedup vs baseline: 1.4052x; 1.4052x over previous
#include <cuda_runtime.h>
#include <math.h>
#include <stdint.h>

#define G 8192
#define S 64
#define D 128
#define H 256
#define EPS 0.01f

// Output layout: rep [G*D] | mixture [G*8] | scale [G] | alpha [G] | beta [G]
#define O_REP   0
#define O_MIX   (G * D)
#define O_SCALE (O_MIX + G * 8)
#define O_ALPHA (O_SCALE + G)
#define O_BETA  (O_ALPHA + G)

// ---------------------------------------------------------------------------
// Kernel 1: per-group statistics -> rep. EXACT round-3 form (proven ~49us).
// ---------------------------------------------------------------------------
__global__ __launch_bounds__(256) void stats_kernel(
    const float* __restrict__ x, const float* __restrict__ y,
    const float* __restrict__ ax, const float* __restrict__ ay,
    float* __restrict__ rep)
{
    const int warp = threadIdx.x >> 5;
    const int lane = threadIdx.x & 31;
    const int g = blockIdx.x * 8 + warp;

    const float4* xg = reinterpret_cast<const float4*>(x + (size_t)g * S * D) + lane;
    const float4  a4 = reinterpret_cast<const float4*>(ax + (size_t)g * D)[lane];
    const float   ayv = ay[g];
    const float*  yg = y + (size_t)g * S;

    float sx0 = 0.f, sx1 = 0.f, sx2 = 0.f, sx3 = 0.f;
    float sp0 = 0.f, sp1 = 0.f, sp2 = 0.f, sp3 = 0.f;
    float sxx = 0.f, sy = 0.f;

#pragma unroll 4
    for (int s = 0; s < S; ++s) {
        float4 xv = xg[s * 32];
        float  yv = __ldg(yg + s);
        float xr0 = xv.x - a4.x;
        float xr1 = xv.y - a4.y;
        float xr2 = xv.z - a4.z;
        float xr3 = xv.w - a4.w;
        float yr  = yv - ayv;
        sx0 += xr0; sx1 += xr1; sx2 += xr2; sx3 += xr3;
        sp0 += xr0 * yr; sp1 += xr1 * yr; sp2 += xr2 * yr; sp3 += xr3 * yr;
        sxx += xr0 * xr0 + xr1 * xr1 + xr2 * xr2 + xr3 * xr3;
        sy  += yr;
    }

    float tot = sx0 + sx1 + sx2 + sx3;
    float sxxT = sxx;
#pragma unroll
    for (int o = 16; o > 0; o >>= 1) {
        tot  += __shfl_xor_sync(0xffffffffu, tot,  o);
        sxxT += __shfl_xor_sync(0xffffffffu, sxxT, o);
    }

    const float nD = (float)(S * D);
    const float var = (sxxT - tot * tot / nD) / (nD - 1.f);
    const float inv = 1.f / var;
    const float invn  = 1.f / (float)S;
    const float invn1 = 1.f / (float)(S - 1);

    float4 r;
    r.x = (sp0 - sx0 * sy * invn) * invn1 * inv;
    r.y = (sp1 - sx1 * sy * invn) * invn1 * inv;
    r.z = (sp2 - sx2 * sy * invn) * invn1 * inv;
    r.w = (sp3 - sx3 * sy * invn) * invn1 * inv;
    reinterpret_cast<float4*>(rep + (size_t)g * D)[lane] = r;
}

// ---------------------------------------------------------------------------
// Kernel 2: MLP head = round-5 tiling (ROWS=32, 8x4 micro-tile) +
// double-buffered cp.async W1 chunks. sH aliased into dead sW buffer.
// smem = 16 + 64 + 10 = 90KB -> 2 CTAs/SM, grid = 256.
// ---------------------------------------------------------------------------
__device__ __forceinline__ float softplus_f(float v) {
    return fmaxf(v, 0.f) + log1pf(expf(-fabsf(v)));
}

__device__ __forceinline__ void cp_async16(uint32_t dst_smem, const void* src) {
    asm volatile("cp.async.cg.shared.global [%0], [%1], 16;"
                 :: "r"(dst_smem), "l"(src) : "memory");
}
__device__ __forceinline__ void cp_commit() {
    asm volatile("cp.async.commit_group;" ::: "memory");
}
__device__ __forceinline__ void cp_wait0() {
    asm volatile("cp.async.wait_group 0;" ::: "memory");
}

#define ROWS 32                 // groups per block
#define KC   32                 // k-chunk depth
#define NCHUNK (D / KC)         // 4

__global__ __launch_bounds__(256, 2) void mlp_kernel(
    const float* __restrict__ rep, const float* __restrict__ W1,
    const float* __restrict__ b1, const float* __restrict__ W2,
    const float* __restrict__ b2, float* __restrict__ out)
{
    __shared__ float sA[ROWS * D];        // 16 KB
    __shared__ float sW[2][KC * H];       // 64 KB (double buffer)
    __shared__ float sW2[H * 10];         // 10 KB

    const int t = threadIdx.x;
    const int rgrp = t >> 6;              // 0..3 -> rows [8*rgrp, 8*rgrp+8)
    const int c0 = (t & 63) * 4;          // cols [c0, c0+4)

    const uint32_t swb0 = (uint32_t)__cvta_generic_to_shared(&sW[0][0]);
    const uint32_t swb1 = (uint32_t)__cvta_generic_to_shared(&sW[1][0]);
    const uint32_t tb16 = (uint32_t)t * 16;

    // preload chunk 0 into sW[0] (async, overlaps sA/sW2 loads below)
#pragma unroll
    for (int i = 0; i < 8; ++i)
        cp_async16(swb0 + tb16 + i * 4096, W1 + 4 * (t + i * 256));
    cp_commit();

    // load A tile (32 rows of rep) and W2
    {
        const float4* src = reinterpret_cast<const float4*>(rep + (size_t)blockIdx.x * ROWS * D);
        float4* dst = reinterpret_cast<float4*>(sA);
#pragma unroll
        for (int i = 0; i < 4; ++i) dst[t + i * 256] = src[t + i * 256];
    }
    for (int i = t; i < H * 10; i += 256) sW2[i] = W2[i];

    float acc[8][4];
#pragma unroll
    for (int r = 0; r < 8; ++r)
#pragma unroll
        for (int j = 0; j < 4; ++j) acc[r][j] = 0.f;

    const float* Abase = sA + rgrp * 8 * D;

    cp_wait0();
    __syncthreads();              // chunk 0 + sA + sW2 visible

#pragma unroll
    for (int c = 0; c < NCHUNK; ++c) {
        // prefetch next chunk into the other buffer
        if (c + 1 < NCHUNK) {
            const uint32_t dstb = ((c + 1) & 1) ? swb1 : swb0;
            const float* src = W1 + (c + 1) * KC * H;
#pragma unroll
            for (int i = 0; i < 8; ++i)
                cp_async16(dstb + tb16 + i * 4096, src + 4 * (t + i * 256));
            cp_commit();
        }

        const float* wbuf = sW[c & 1];
#pragma unroll
        for (int kk = 0; kk < KC; ++kk) {
            const int k = c * KC + kk;
            float4 w = *reinterpret_cast<const float4*>(wbuf + kk * H + c0);
            float a[8];
#pragma unroll
            for (int r = 0; r < 8; ++r) a[r] = Abase[r * D + k];  // broadcast
#pragma unroll
            for (int r = 0; r < 8; ++r) {
                acc[r][0] += a[r] * w.x;
                acc[r][1] += a[r] * w.y;
                acc[r][2] += a[r] * w.z;
                acc[r][3] += a[r] * w.w;
            }
        }

        if (c + 1 < NCHUNK) {
            cp_wait0();
            __syncthreads();      // next chunk ready; all done reading this one
        }
    }

    // tanh -> sH (aliased into sW, now dead)
    float* sH = &sW[0][0];        // 32*256 floats = exactly sW[0]
    __syncthreads();              // everyone done reading sW buffers
    {
        float4 bb = reinterpret_cast<const float4*>(b1)[c0 >> 2];
#pragma unroll
        for (int r = 0; r < 8; ++r) {
            float4 h;
            h.x = tanhf(acc[r][0] + bb.x);
            h.y = tanhf(acc[r][1] + bb.y);
            h.z = tanhf(acc[r][2] + bb.z);
            h.w = tanhf(acc[r][3] + bb.w);
            *reinterpret_cast<float4*>(sH + (rgrp * 8 + r) * H + c0) = h;
        }
    }
    __syncthreads();

    // GEMM2 + epilogue: warp w handles groups [4w, 4w+4)
    const int warp = t >> 5;
    const int lane = t & 31;

#pragma unroll
    for (int i = 0; i < 4; ++i) {
        const int row = warp * 4 + i;
        const float* hrow = sH + row * H;

        float p[10];
#pragma unroll
        for (int k = 0; k < 10; ++k) p[k] = 0.f;

#pragma unroll
        for (int j = 0; j < 8; ++j) {
            float hv = hrow[lane + 32 * j];
            const float* w2r = sW2 + (lane + 32 * j) * 10;
#pragma unroll
            for (int k = 0; k < 10; ++k) p[k] += hv * w2r[k];
        }
#pragma unroll
        for (int k = 0; k < 10; ++k) {
#pragma unroll
            for (int o = 16; o > 0; o >>= 1)
                p[k] += __shfl_xor_sync(0xffffffffu, p[k], o);
        }

        if (lane == 0) {
            const int g = blockIdx.x * ROWS + row;
            float o0 = p[0] + __ldg(b2 + 0);
            float o1 = p[1] + __ldg(b2 + 1);
            float alpha = softplus_f(o0) * (1.f - EPS) + EPS;
            float beta  = softplus_f(o1) * (1.f - EPS) + EPS;

            float lg[8];
            float mx = -3.4e38f;
#pragma unroll
            for (int k = 0; k < 8; ++k) {
                lg[k] = p[2 + k] + __ldg(b2 + 2 + k);
                mx = fmaxf(mx, lg[k]);
            }
            float se = 0.f;
#pragma unroll
            for (int k = 0; k < 8; ++k) { lg[k] = expf(lg[k] - mx); se += lg[k]; }
            float inv_se = 1.f / se;
#pragma unroll
            for (int k = 0; k < 8; ++k) out[O_MIX + (size_t)g * 8 + k] = lg[k] * inv_se;

            out[O_SCALE + g] = sqrtf(beta / alpha);
            out[O_ALPHA + g] = alpha;
            out[O_BETA  + g] = beta;
        }
    }
}

// ---------------------------------------------------------------------------
extern "C" void kernel_launch(void* const* d_in, const int* in_sizes, int n_in,
                              void* d_out, int out_size)
{
    (void)in_sizes; (void)n_in; (void)out_size;
    // inputs: 0=index(int32), 1=x, 2=y, 3=anchor_x, 4=anchor_y, 5=W1, 6=b1, 7=W2, 8=b2
    const float* x  = (const float*)d_in[1];
    const float* y  = (const float*)d_in[2];
    const float* ax = (const float*)d_in[3];
    const float* ay = (const float*)d_in[4];
    const float* W1 = (const float*)d_in[5];
    const float* b1 = (const float*)d_in[6];
    const float* W2 = (const float*)d_in[7];
    const float* b2 = (const float*)d_in[8];
    float* out = (float*)d_out;

    stats_kernel<<<G / 8, 256>>>(x, y, ax, ay, out + O_REP);
    mlp_kernel<<<G / ROWS, 256>>>(out + O_REP, W1, b1, W2, b2, out);
}

// round 8
// speedup vs baseline: 1.4263x; 1.0151x over previous
#include <cuda_runtime.h>
#include <math.h>

#define G 8192
#define S 64
#define D 128
#define H 256
#define EPS 0.01f

// Output layout: rep [G*D] | mixture [G*8] | scale [G] | alpha [G] | beta [G]
#define O_REP   0
#define O_MIX   (G * D)
#define O_SCALE (O_MIX + G * 8)
#define O_ALPHA (O_SCALE + G)
#define O_BETA  (O_ALPHA + G)

#define TILE 8                  // groups per block (both roles)
#define STAT_BLOCKS (G / TILE)  // 1024

// Cross-block ready flags. Zero at load; each consumer resets its flag after
// consuming, so every run (correctness, every graph replay) starts from 0.
__device__ int g_flags[STAT_BLOCKS];

__device__ __forceinline__ float softplus_f(float v) {
    return fmaxf(v, 0.f) + log1pf(expf(-fabsf(v)));
}

// ---------------------------------------------------------------------------
// One launch, two roles.
//   bid <  1024 : stats for groups [8*bid, 8*bid+8)  (proven R3 body)
//   bid >= 1024 : MLP for the same 8 groups, spin-wait on producer flag
// ---------------------------------------------------------------------------
__global__ __launch_bounds__(256) void fused_kernel(
    const float* __restrict__ x, const float* __restrict__ y,
    const float* __restrict__ ax, const float* __restrict__ ay,
    const float* __restrict__ W1, const float* __restrict__ b1,
    const float* __restrict__ W2, const float* __restrict__ b2,
    float* __restrict__ out)
{
    __shared__ float sA[TILE * D];     // 4 KB
    __shared__ float sH[TILE * H];     // 8 KB
    __shared__ float sW2[H * 10];      // 10 KB

    const int t = threadIdx.x;
    const int bid = blockIdx.x;
    const int warp = t >> 5;
    const int lane = t & 31;

    if (bid < STAT_BLOCKS) {
        // ================= stats role =================
        const int g = bid * 8 + warp;

        const float4* xg = reinterpret_cast<const float4*>(x + (size_t)g * S * D) + lane;
        const float4  a4 = reinterpret_cast<const float4*>(ax + (size_t)g * D)[lane];
        const float   ayv = ay[g];
        const float*  yg = y + (size_t)g * S;

        float sx0 = 0.f, sx1 = 0.f, sx2 = 0.f, sx3 = 0.f;
        float sp0 = 0.f, sp1 = 0.f, sp2 = 0.f, sp3 = 0.f;
        float sxx = 0.f, sy = 0.f;

#pragma unroll 4
        for (int s = 0; s < S; ++s) {
            float4 xv = xg[s * 32];
            float  yv = __ldg(yg + s);
            float xr0 = xv.x - a4.x;
            float xr1 = xv.y - a4.y;
            float xr2 = xv.z - a4.z;
            float xr3 = xv.w - a4.w;
            float yr  = yv - ayv;
            sx0 += xr0; sx1 += xr1; sx2 += xr2; sx3 += xr3;
            sp0 += xr0 * yr; sp1 += xr1 * yr; sp2 += xr2 * yr; sp3 += xr3 * yr;
            sxx += xr0 * xr0 + xr1 * xr1 + xr2 * xr2 + xr3 * xr3;
            sy  += yr;
        }

        float tot = sx0 + sx1 + sx2 + sx3;
        float sxxT = sxx;
#pragma unroll
        for (int o = 16; o > 0; o >>= 1) {
            tot  += __shfl_xor_sync(0xffffffffu, tot,  o);
            sxxT += __shfl_xor_sync(0xffffffffu, sxxT, o);
        }

        const float nD = (float)(S * D);
        const float var = (sxxT - tot * tot / nD) / (nD - 1.f);
        const float inv = 1.f / var;
        const float invn  = 1.f / (float)S;
        const float invn1 = 1.f / (float)(S - 1);

        float4 r;
        r.x = (sp0 - sx0 * sy * invn) * invn1 * inv;
        r.y = (sp1 - sx1 * sy * invn) * invn1 * inv;
        r.z = (sp2 - sx2 * sy * invn) * invn1 * inv;
        r.w = (sp3 - sx3 * sy * invn) * invn1 * inv;
        reinterpret_cast<float4*>(out + O_REP + (size_t)g * D)[lane] = r;

        __syncthreads();
        __threadfence();
        if (t == 0) atomicExch(&g_flags[bid], 1);
        return;
    }

    // ================= MLP role =================
    const int m = bid - STAT_BLOCKS;      // partner stats block; groups 8m..8m+7
    const float* rep = out + O_REP;

    // independent prefetch while waiting
    for (int i = t; i < H * 10; i += 256) sW2[i] = W2[i];

    if (t == 0) {
        while (atomicAdd(&g_flags[m], 0) == 0) __nanosleep(64);
        g_flags[m] = 0;                   // reset for next graph replay
    }
    __syncthreads();
    __threadfence();

    // load A tile (8 rows x 128) : 256 float4, one per thread
    reinterpret_cast<float4*>(sA)[t] =
        reinterpret_cast<const float4*>(rep + (size_t)m * TILE * D)[t];
    __syncthreads();

    // ---- GEMM1 + tanh: thread = rows {rr, rr+1} x cols [c0, c0+4) ----
    {
        const int rr = (t >> 6) * 2;
        const int c0 = (t & 63) * 4;
        const float* A0 = sA + rr * D;
        const float* A1 = A0 + D;
        const float4* W1v = reinterpret_cast<const float4*>(W1) + (c0 >> 2);

        float4 acc0 = {0.f, 0.f, 0.f, 0.f};
        float4 acc1 = {0.f, 0.f, 0.f, 0.f};
#pragma unroll 8
        for (int k = 0; k < D; ++k) {
            float4 w = W1v[k * (H / 4)];
            float a0 = A0[k];
            float a1 = A1[k];
            acc0.x += a0 * w.x; acc0.y += a0 * w.y;
            acc0.z += a0 * w.z; acc0.w += a0 * w.w;
            acc1.x += a1 * w.x; acc1.y += a1 * w.y;
            acc1.z += a1 * w.z; acc1.w += a1 * w.w;
        }
        float4 bb = reinterpret_cast<const float4*>(b1)[c0 >> 2];
        float4 h0, h1;
        h0.x = tanhf(acc0.x + bb.x); h0.y = tanhf(acc0.y + bb.y);
        h0.z = tanhf(acc0.z + bb.z); h0.w = tanhf(acc0.w + bb.w);
        h1.x = tanhf(acc1.x + bb.x); h1.y = tanhf(acc1.y + bb.y);
        h1.z = tanhf(acc1.z + bb.z); h1.w = tanhf(acc1.w + bb.w);
        reinterpret_cast<float4*>(sH + rr * H + c0)[0] = h0;
        reinterpret_cast<float4*>(sH + (rr + 1) * H + c0)[0] = h1;
    }
    __syncthreads();

    // ---- GEMM2 + epilogue: warp = group ----
    {
        float p[10];
#pragma unroll
        for (int k = 0; k < 10; ++k) p[k] = 0.f;

        const float* hrow = sH + warp * H;
#pragma unroll
        for (int j = 0; j < 8; ++j) {
            float hv = hrow[lane + 32 * j];
            const float* w2r = sW2 + (lane + 32 * j) * 10;
#pragma unroll
            for (int k = 0; k < 10; ++k) p[k] += hv * w2r[k];
        }
#pragma unroll
        for (int k = 0; k < 10; ++k) {
#pragma unroll
            for (int o = 16; o > 0; o >>= 1)
                p[k] += __shfl_xor_sync(0xffffffffu, p[k], o);
        }

        if (lane == 0) {
            const int g = m * TILE + warp;
            float o0 = p[0] + __ldg(b2 + 0);
            float o1 = p[1] + __ldg(b2 + 1);
            float alpha = softplus_f(o0) * (1.f - EPS) + EPS;
            float beta  = softplus_f(o1) * (1.f - EPS) + EPS;

            float lg[8];
            float mx = -3.4e38f;
#pragma unroll
            for (int k = 0; k < 8; ++k) {
                lg[k] = p[2 + k] + __ldg(b2 + 2 + k);
                mx = fmaxf(mx, lg[k]);
            }
            float se = 0.f;
#pragma unroll
            for (int k = 0; k < 8; ++k) { lg[k] = expf(lg[k] - mx); se += lg[k]; }
            float inv_se = 1.f / se;
#pragma unroll
            for (int k = 0; k < 8; ++k) out[O_MIX + (size_t)g * 8 + k] = lg[k] * inv_se;

            out[O_SCALE + g] = sqrtf(beta / alpha);
            out[O_ALPHA + g] = alpha;
            out[O_BETA  + g] = beta;
        }
    }
}

// ---------------------------------------------------------------------------
extern "C" void kernel_launch(void* const* d_in, const int* in_sizes, int n_in,
                              void* d_out, int out_size)
{
    (void)in_sizes; (void)n_in; (void)out_size;
    // inputs: 0=index(int32), 1=x, 2=y, 3=anchor_x, 4=anchor_y, 5=W1, 6=b1, 7=W2, 8=b2
    const float* x  = (const float*)d_in[1];
    const float* y  = (const float*)d_in[2];
    const float* ax = (const float*)d_in[3];
    const float* ay = (const float*)d_in[4];
    const float* W1 = (const float*)d_in[5];
    const float* b1 = (const float*)d_in[6];
    const float* W2 = (const float*)d_in[7];
    const float* b2 = (const float*)d_in[8];
    float* out = (float*)d_out;

    fused_kernel<<<2 * STAT_BLOCKS, 256>>>(x, y, ax, ay, W1, b1, W2, b2, out);
}